// round 14
// baseline (speedup 1.0000x reference)
#include <cuda_runtime.h>

#define NN 50000
#define TT 10
#define EE 1000000
#define HH 8

#define NBLK 296          // = 2 * 148 SMs; all resident (>=2 blocks/SM guaranteed)
#define NTHR 256
#define NPB  169          // ceil(NN / NBLK); 296*169 = 50024 >= 50000

typedef unsigned long long u64;

// ---------------- device scratch (no allocations allowed) ----------------
__device__ float g_s[NN];             // per-node sigmoid(message MLP)
__device__ float g_agg[NN];           // per-node aggregated messages
__device__ float g_eaT[TT * EE];      // edge_attr transposed to [T,E]
__device__ float g_x0T[TT * NN];      // x[:,t,0] transposed to [T,N]
__device__ float g_x1T[TT * NN];      // x[:,t,1] transposed to [T,N]

// ---------------- global barrier state ----------------
__device__ unsigned g_bar_cnt;
__device__ volatile unsigned g_bar_gen;

// ---------------- weights: packed staging + constant bank ----------------
struct __align__(16) Weights {
    float m1w1[9 * 32];
    float m1b1[32];
    float m1w2[32 * 32];
    float m1b2[32];
    float m1w3[32];
    float m1b3;
    float pad[3];
    float m2w1[10 * 32];
    float m2b1[32];
    float m2w2[32 * 8];
    float m2b2[8];
    float ow1[8 * 16];
    float ob1[16];
    float ow2[16];
    float ob2;
    float pad2[3];
};

__device__   Weights g_wstage;   // staging, written by pack kernel
__constant__ Weights cW;         // read by persistent kernel

struct WPtrs {
    const float *m1w1, *m1b1, *m1w2, *m1b2, *m1w3, *m1b3;
    const float *m2w1, *m2b1, *m2w2, *m2b2;
    const float *ow1, *ob1, *ow2, *ob2;
};

__global__ void pack_weights_kernel(const WPtrs p) {
    const int tid = threadIdx.x, nt = blockDim.x;
    for (int i = tid; i < 9 * 32; i += nt)  g_wstage.m1w1[i] = p.m1w1[i];
    for (int i = tid; i < 32; i += nt)      g_wstage.m1b1[i] = p.m1b1[i];
    for (int i = tid; i < 32 * 32; i += nt) g_wstage.m1w2[i] = p.m1w2[i];
    for (int i = tid; i < 32; i += nt)      g_wstage.m1b2[i] = p.m1b2[i];
    for (int i = tid; i < 32; i += nt)      g_wstage.m1w3[i] = p.m1w3[i];
    for (int i = tid; i < 10 * 32; i += nt) g_wstage.m2w1[i] = p.m2w1[i];
    for (int i = tid; i < 32; i += nt)      g_wstage.m2b1[i] = p.m2b1[i];
    for (int i = tid; i < 32 * 8; i += nt)  g_wstage.m2w2[i] = p.m2w2[i];
    for (int i = tid; i < 8; i += nt)       g_wstage.m2b2[i] = p.m2b2[i];
    for (int i = tid; i < 8 * 16; i += nt)  g_wstage.ow1[i] = p.ow1[i];
    for (int i = tid; i < 16; i += nt)      g_wstage.ob1[i] = p.ob1[i];
    for (int i = tid; i < 16; i += nt)      g_wstage.ow2[i] = p.ow2[i];
    if (tid == 0) { g_wstage.m1b3 = p.m1b3[0]; g_wstage.ob2 = p.ob2[0]; }
}

// ---------------- f32x2 packed primitives (Blackwell) ----------------
__device__ __forceinline__ u64 pk2(float lo, float hi) {
    u64 r; asm("mov.b64 %0, {%1,%2};" : "=l"(r) : "f"(lo), "f"(hi)); return r;
}
__device__ __forceinline__ void upk2(u64 v, float& lo, float& hi) {
    asm("mov.b64 {%0,%1}, %2;" : "=f"(lo), "=f"(hi) : "l"(v));
}
__device__ __forceinline__ u64 dup2(float x) { return pk2(x, x); }
__device__ __forceinline__ u64 ffma2(u64 a, u64 b, u64 c) {
    u64 d; asm("fma.rn.f32x2 %0, %1, %2, %3;" : "=l"(d) : "l"(a), "l"(b), "l"(c)); return d;
}
__device__ __forceinline__ u64 relu2(u64 v) {
    float lo, hi; upk2(v, lo, hi);
    return pk2(fmaxf(lo, 0.0f), fmaxf(hi, 0.0f));
}

// ---------------- branch-free fast activations ----------------
__device__ __forceinline__ float rcp_approx(float x) {
    float r; asm("rcp.approx.f32 %0, %1;" : "=f"(r) : "f"(x)); return r;
}
__device__ __forceinline__ float fast_sigmoid(float z) {
    return rcp_approx(1.0f + __expf(-z));
}
// tanh for x >= 0 (post-ReLU): tanh(x) = 1 - 2/(e^{2x}+1), branch-free.
__device__ __forceinline__ float fast_tanh_nonneg(float x) {
    x = fminf(x, 15.0f);
    float e = __expf(2.0f * x);
    return fmaf(-2.0f, rcp_approx(e + 1.0f), 1.0f);
}

// ---------------- grid-wide barrier (all NBLK blocks resident) ----------------
__device__ __forceinline__ void grid_barrier() {
    __threadfence();              // release: drain STG/RED to L2 before arriving
    __syncthreads();
    if (threadIdx.x == 0) {
        unsigned gen = g_bar_gen;
        if (atomicAdd(&g_bar_cnt, 1u) == NBLK - 1) {
            g_bar_cnt = 0;
            __threadfence();
            g_bar_gen = gen + 1;  // volatile store releases everyone
        } else {
            while (g_bar_gen == gen) { __nanosleep(32); }
        }
    }
    __syncthreads();
}

// ===================== f32x2 MLPs, weights from __constant__ =====================

// Message MLP [x0, h(8)] -> 32 -> relu -> 32 -> relu -> 1 -> sigmoid
__device__ __forceinline__ float mlp1(u64 x0d, const u64 hd[HH]) {
    u64 a2[16];
    {
        const ulonglong2* bv = (const ulonglong2*)cW.m1b1;
        const ulonglong2* wv = (const ulonglong2*)cW.m1w1;   // row 0 (x0)
        #pragma unroll
        for (int j = 0; j < 8; j++) {
            ulonglong2 b = bv[j]; ulonglong2 w = wv[j];
            a2[2*j]   = ffma2(x0d, w.x, b.x);
            a2[2*j+1] = ffma2(x0d, w.y, b.y);
        }
    }
    #pragma unroll
    for (int i = 0; i < HH; i++) {
        u64 hi = hd[i];
        const ulonglong2* wr = (const ulonglong2*)(cW.m1w1 + (i + 1) * 32);
        #pragma unroll
        for (int j = 0; j < 8; j++) {
            ulonglong2 w = wr[j];
            a2[2*j]   = ffma2(hi, w.x, a2[2*j]);
            a2[2*j+1] = ffma2(hi, w.y, a2[2*j+1]);
        }
    }
    float a[32];
    #pragma unroll
    for (int j = 0; j < 16; j++) {
        u64 r = relu2(a2[j]);
        upk2(r, a[2*j], a[2*j+1]);
    }

    u64 b2[16];
    {
        const ulonglong2* bv = (const ulonglong2*)cW.m1b2;
        #pragma unroll
        for (int j = 0; j < 8; j++) { ulonglong2 b = bv[j]; b2[2*j] = b.x; b2[2*j+1] = b.y; }
    }
    #pragma unroll
    for (int i = 0; i < 32; i++) {
        u64 ai = dup2(a[i]);
        const ulonglong2* wr = (const ulonglong2*)(cW.m1w2 + i * 32);
        #pragma unroll
        for (int j = 0; j < 8; j++) {
            ulonglong2 w = wr[j];
            b2[2*j]   = ffma2(ai, w.x, b2[2*j]);
            b2[2*j+1] = ffma2(ai, w.y, b2[2*j+1]);
        }
    }
    u64 z2 = 0ULL;
    {
        const ulonglong2* wv = (const ulonglong2*)cW.m1w3;
        #pragma unroll
        for (int j = 0; j < 8; j++) {
            ulonglong2 w = wv[j];
            z2 = ffma2(relu2(b2[2*j]),   w.x, z2);
            z2 = ffma2(relu2(b2[2*j+1]), w.y, z2);
        }
    }
    float zl, zh; upk2(z2, zl, zh);
    return fast_sigmoid(zl + zh + cW.m1b3);
}

// Update MLP [x1,h(8),agg](10) -> 32 -> relu -> 8 -> relu -> tanh
__device__ __forceinline__ void mlp2(const u64 in2[10], float hnew[HH]) {
    u64 a2[16];
    {
        const ulonglong2* bv = (const ulonglong2*)cW.m2b1;
        #pragma unroll
        for (int j = 0; j < 8; j++) { ulonglong2 b = bv[j]; a2[2*j] = b.x; a2[2*j+1] = b.y; }
    }
    #pragma unroll
    for (int i = 0; i < 10; i++) {
        u64 vi = in2[i];
        const ulonglong2* wr = (const ulonglong2*)(cW.m2w1 + i * 32);
        #pragma unroll
        for (int j = 0; j < 8; j++) {
            ulonglong2 w = wr[j];
            a2[2*j]   = ffma2(vi, w.x, a2[2*j]);
            a2[2*j+1] = ffma2(vi, w.y, a2[2*j+1]);
        }
    }
    float a[32];
    #pragma unroll
    for (int j = 0; j < 16; j++) {
        u64 r = relu2(a2[j]);
        upk2(r, a[2*j], a[2*j+1]);
    }

    u64 b8[4];
    {
        const ulonglong2* bv = (const ulonglong2*)cW.m2b2;
        ulonglong2 b0 = bv[0], b1 = bv[1];
        b8[0] = b0.x; b8[1] = b0.y; b8[2] = b1.x; b8[3] = b1.y;
    }
    #pragma unroll
    for (int i = 0; i < 32; i++) {
        u64 ai = dup2(a[i]);
        const ulonglong2* wr = (const ulonglong2*)(cW.m2w2 + i * 8);
        ulonglong2 w0 = wr[0], w1 = wr[1];
        b8[0] = ffma2(ai, w0.x, b8[0]); b8[1] = ffma2(ai, w0.y, b8[1]);
        b8[2] = ffma2(ai, w1.x, b8[2]); b8[3] = ffma2(ai, w1.y, b8[3]);
    }
    // hidden_new = tanh(relu(z2))
    #pragma unroll
    for (int k = 0; k < 4; k++) {
        float lo, hi; upk2(relu2(b8[k]), lo, hi);
        hnew[2*k]   = fast_tanh_nonneg(lo);
        hnew[2*k+1] = fast_tanh_nonneg(hi);
    }
}

// Readout hidden(8) -> 16 -> relu -> 1 -> sigmoid (takes pre-dup'd hidden)
__device__ __forceinline__ float node_out(const u64 hd[HH]) {
    u64 o2[8];
    {
        const ulonglong2* bv = (const ulonglong2*)cW.ob1;
        #pragma unroll
        for (int m = 0; m < 4; m++) { ulonglong2 b = bv[m]; o2[2*m] = b.x; o2[2*m+1] = b.y; }
    }
    #pragma unroll
    for (int i = 0; i < HH; i++) {
        u64 hi = hd[i];
        const ulonglong2* wr = (const ulonglong2*)(cW.ow1 + i * 16);
        #pragma unroll
        for (int m = 0; m < 4; m++) {
            ulonglong2 w = wr[m];
            o2[2*m]   = ffma2(hi, w.x, o2[2*m]);
            o2[2*m+1] = ffma2(hi, w.y, o2[2*m+1]);
        }
    }
    u64 z2 = 0ULL;
    {
        const ulonglong2* wv = (const ulonglong2*)cW.ow2;
        #pragma unroll
        for (int m = 0; m < 4; m++) {
            ulonglong2 w = wv[m];
            z2 = ffma2(relu2(o2[2*m]),   w.x, z2);
            z2 = ffma2(relu2(o2[2*m+1]), w.y, z2);
        }
    }
    float zl, zh; upk2(z2, zl, zh);
    return fast_sigmoid(zl + zh + cW.ob2);
}

// ===================== THE persistent kernel =====================
// Phases: transpose | barrier | prologue | barrier |
//         10x [ deferred-readout + edges | barrier | update(+mlp1 next) | barrier ]
//         final readout.
// Hidden state lives in registers (hd) for the entire sequence.
__global__ void __launch_bounds__(NTHR, 2)
persistent_kernel(const float* __restrict__ ea, const float* __restrict__ x,
                  const int* __restrict__ ei, float* __restrict__ out) {
    const int b = blockIdx.x, tid = threadIdx.x;
    const int gtid = b * NTHR + tid;
    const int nthr = NBLK * NTHR;

    // ---- Phase T: one-time transposes (grid-stride) ----
    for (int e = gtid; e < EE; e += nthr) {
        #pragma unroll
        for (int t = 0; t < TT; t++) g_eaT[t * EE + e] = ea[e * TT + t];
    }
    for (int m = gtid; m < NN; m += nthr) {
        #pragma unroll
        for (int t = 0; t < TT; t++) {
            float2 v = ((const float2*)x)[m * TT + t];
            g_x0T[t * NN + m] = v.x;
            g_x1T[t * NN + m] = v.y;
        }
    }
    grid_barrier();

    // ---- my node (fixed for the whole sequence) ----
    const int n = b * NPB + tid;
    const bool active = (tid < NPB) && (n < NN);

    u64 hd[HH];   // duplicated-pair hidden state, register-resident
    #pragma unroll
    for (int i = 0; i < HH; i++) hd[i] = 0ULL;

    // ---- prologue: s_0 = mlp1(x0_0, h=0); agg = 0 ----
    if (active) {
        u64 x0d = dup2(g_x0T[n]);
        g_s[n] = mlp1(x0d, hd);
        g_agg[n] = 0.0f;
    }
    grid_barrier();

    // ---- frame loop ----
    for (int t = 0; t < TT; t++) {
        // deferred readout of previous frame (free compute in the memory-bound phase)
        if (t > 0 && active) out[(t - 1) * NN + n] = node_out(hd);

        // edge phase: agg[dst] += s[src] * ea ; 4 edges/thread, grid-stride
        for (int q = gtid; q < EE / 4; q += nthr) {
            int4 s4 = ((const int4*)(ei + t * EE))[q];
            int4 d4 = ((const int4*)(ei + (TT + t) * EE))[q];
            float4 a4 = ((const float4*)(g_eaT + t * EE))[q];
            atomicAdd(&g_agg[d4.x], __ldcg(&g_s[s4.x]) * a4.x);
            atomicAdd(&g_agg[d4.y], __ldcg(&g_s[s4.y]) * a4.y);
            atomicAdd(&g_agg[d4.z], __ldcg(&g_s[s4.z]) * a4.z);
            atomicAdd(&g_agg[d4.w], __ldcg(&g_s[s4.w]) * a4.w);
        }
        grid_barrier();   // all agg complete

        // update phase: h <- tanh(relu(mlp2([x1, h, agg]))) ; s,agg for next frame
        if (active) {
            u64 in2[10];
            in2[0] = dup2(g_x1T[t * NN + n]);
            #pragma unroll
            for (int i = 0; i < HH; i++) in2[1 + i] = hd[i];
            in2[9] = dup2(__ldcg(&g_agg[n]));   // identity norm (mean 0, var 1)

            float hn[HH];
            mlp2(in2, hn);
            #pragma unroll
            for (int i = 0; i < HH; i++) hd[i] = dup2(hn[i]);

            if (t < TT - 1) {
                u64 x0d = dup2(g_x0T[(t + 1) * NN + n]);
                g_s[n] = mlp1(x0d, hd);
                g_agg[n] = 0.0f;
            }
        }
        grid_barrier();   // s / agg-reset visible before next edge phase
    }

    // final frame readout
    if (active) out[(TT - 1) * NN + n] = node_out(hd);
}

// ---------------- launch ----------------
extern "C" void kernel_launch(void* const* d_in, const int* in_sizes, int n_in,
                              void* d_out, int out_size) {
    const float* x  = (const float*)d_in[0];
    const int*   ei = (const int*)d_in[1];
    const float* ea = (const float*)d_in[2];
    WPtrs p;
    p.m1w1 = (const float*)d_in[3];  p.m1b1 = (const float*)d_in[4];
    p.m1w2 = (const float*)d_in[5];  p.m1b2 = (const float*)d_in[6];
    p.m1w3 = (const float*)d_in[7];  p.m1b3 = (const float*)d_in[8];
    p.m2w1 = (const float*)d_in[9];  p.m2b1 = (const float*)d_in[10];
    p.m2w2 = (const float*)d_in[11]; p.m2b2 = (const float*)d_in[12];
    p.ow1  = (const float*)d_in[13]; p.ob1  = (const float*)d_in[14];
    p.ow2  = (const float*)d_in[15]; p.ob2  = (const float*)d_in[16];
    float* out = (float*)d_out;

    // Stage weights, then copy into the constant bank (all graph-capture legal).
    pack_weights_kernel<<<1, 256>>>(p);
    void* cw_addr = nullptr;
    void* st_addr = nullptr;
    cudaGetSymbolAddress(&cw_addr, cW);
    cudaGetSymbolAddress(&st_addr, g_wstage);
    cudaMemcpyAsync(cw_addr, st_addr, sizeof(Weights), cudaMemcpyDeviceToDevice, 0);

    persistent_kernel<<<NBLK, NTHR>>>(ea, x, ei, out);
}

// round 17
// speedup vs baseline: 1.1252x; 1.1252x over previous
#include <cuda_runtime.h>

#define NN 50000
#define TT 10
#define EE 1000000
#define HH 8

#define NPAIR 25000          // nodes paired: (p, p+NPAIR)
#define UPD_BLK 148          // 1 block per SM, perfect balance
#define UPD_THR 176          // 5.5 warps; 148*176 = 26048 >= 25000

typedef unsigned long long u64;

// ---------------- device scratch (no allocations allowed) ----------------
__device__ u64   g_hpack[HH * NPAIR]; // hidden, packed pairs, [i*NPAIR + p]
__device__ float g_s[NN];             // per-node sigmoid(message MLP)
__device__ float g_agg[NN];           // per-node aggregated messages
__device__ float g_eaT[TT * EE];      // edge_attr transposed to [T,E]
__device__ float g_x0T[TT * NN];      // x[:,t,0] transposed to [T,N]
__device__ float g_x1T[TT * NN];      // x[:,t,1] transposed to [T,N]

// ---------------- weights: packed staging + constant bank ----------------
struct __align__(16) Weights {
    float m1w1[9 * 32];
    float m1b1[32];
    float m1w2[32 * 32];
    float m1b2[32];
    float m1w3[32];
    float m1b3;
    float pad[3];
    float m2w1[10 * 32];
    float m2b1[32];
    float m2w2[32 * 8];
    float m2b2[8];
    float ow1[8 * 16];
    float ob1[16];
    float ow2[16];
    float ob2;
    float pad2[3];
};

__device__   Weights g_wstage;
__constant__ Weights cW;

struct WPtrs {
    const float *m1w1, *m1b1, *m1w2, *m1b2, *m1w3, *m1b3;
    const float *m2w1, *m2b1, *m2w2, *m2b2;
    const float *ow1, *ob1, *ow2, *ob2;
};

__global__ void pack_weights_kernel(const WPtrs p) {
    const int tid = threadIdx.x, nt = blockDim.x;
    for (int i = tid; i < 9 * 32; i += nt)  g_wstage.m1w1[i] = p.m1w1[i];
    for (int i = tid; i < 32; i += nt)      g_wstage.m1b1[i] = p.m1b1[i];
    for (int i = tid; i < 32 * 32; i += nt) g_wstage.m1w2[i] = p.m1w2[i];
    for (int i = tid; i < 32; i += nt)      g_wstage.m1b2[i] = p.m1b2[i];
    for (int i = tid; i < 32; i += nt)      g_wstage.m1w3[i] = p.m1w3[i];
    for (int i = tid; i < 10 * 32; i += nt) g_wstage.m2w1[i] = p.m2w1[i];
    for (int i = tid; i < 32; i += nt)      g_wstage.m2b1[i] = p.m2b1[i];
    for (int i = tid; i < 32 * 8; i += nt)  g_wstage.m2w2[i] = p.m2w2[i];
    for (int i = tid; i < 8; i += nt)       g_wstage.m2b2[i] = p.m2b2[i];
    for (int i = tid; i < 8 * 16; i += nt)  g_wstage.ow1[i] = p.ow1[i];
    for (int i = tid; i < 16; i += nt)      g_wstage.ob1[i] = p.ob1[i];
    for (int i = tid; i < 16; i += nt)      g_wstage.ow2[i] = p.ow2[i];
    if (tid == 0) { g_wstage.m1b3 = p.m1b3[0]; g_wstage.ob2 = p.ob2[0]; }
}

// ---------------- f32x2 packed primitives (Blackwell) ----------------
__device__ __forceinline__ u64 pk2(float lo, float hi) {
    u64 r; asm("mov.b64 %0, {%1,%2};" : "=l"(r) : "f"(lo), "f"(hi)); return r;
}
__device__ __forceinline__ void upk2(u64 v, float& lo, float& hi) {
    asm("mov.b64 {%0,%1}, %2;" : "=f"(lo), "=f"(hi) : "l"(v));
}
__device__ __forceinline__ u64 dup2(float x) { return pk2(x, x); }
__device__ __forceinline__ u64 ffma2(u64 a, u64 b, u64 c) {
    u64 d; asm("fma.rn.f32x2 %0, %1, %2, %3;" : "=l"(d) : "l"(a), "l"(b), "l"(c)); return d;
}
__device__ __forceinline__ u64 relu2(u64 v) {
    float lo, hi; upk2(v, lo, hi);
    return pk2(fmaxf(lo, 0.0f), fmaxf(hi, 0.0f));
}

// ---------------- branch-free fast activations ----------------
__device__ __forceinline__ float rcp_approx(float x) {
    float r; asm("rcp.approx.f32 %0, %1;" : "=f"(r) : "f"(x)); return r;
}
__device__ __forceinline__ float fast_sigmoid(float z) {
    return rcp_approx(1.0f + __expf(-z));
}
// tanh for x >= 0 (post-ReLU)
__device__ __forceinline__ float fast_tanh_nonneg(float x) {
    x = fminf(x, 15.0f);
    float e = __expf(2.0f * x);
    return fmaf(-2.0f, rcp_approx(e + 1.0f), 1.0f);
}

// ===================== NODE-PAIR MLPs =====================
// Every u64 = (nodeA, nodeB). Activations stay packed between layers;
// each scalar weight is loaded once (const bank) and dup2'd for both nodes.

// Message MLP [x0,h(8)] -> 32 -> relu -> 32 -> relu -> 1 -> sigmoid (both nodes)
__device__ __forceinline__ void mlp1_pair(u64 x0, const u64 hd[HH],
                                          float& sA, float& sB) {
    u64 acc[32];
    {
        const float4* bv = (const float4*)cW.m1b1;
        const float4* wv = (const float4*)cW.m1w1;   // row 0 (x0)
        #pragma unroll
        for (int j4 = 0; j4 < 8; j4++) {
            float4 b = bv[j4]; float4 w = wv[j4];
            acc[4*j4+0] = ffma2(x0, dup2(w.x), dup2(b.x));
            acc[4*j4+1] = ffma2(x0, dup2(w.y), dup2(b.y));
            acc[4*j4+2] = ffma2(x0, dup2(w.z), dup2(b.z));
            acc[4*j4+3] = ffma2(x0, dup2(w.w), dup2(b.w));
        }
    }
    #pragma unroll
    for (int i = 0; i < HH; i++) {
        u64 hi = hd[i];
        const float4* wr = (const float4*)(cW.m1w1 + (i + 1) * 32);
        #pragma unroll
        for (int j4 = 0; j4 < 8; j4++) {
            float4 w = wr[j4];
            acc[4*j4+0] = ffma2(hi, dup2(w.x), acc[4*j4+0]);
            acc[4*j4+1] = ffma2(hi, dup2(w.y), acc[4*j4+1]);
            acc[4*j4+2] = ffma2(hi, dup2(w.z), acc[4*j4+2]);
            acc[4*j4+3] = ffma2(hi, dup2(w.w), acc[4*j4+3]);
        }
    }
    #pragma unroll
    for (int j = 0; j < 32; j++) acc[j] = relu2(acc[j]);

    // layer 2+3 in two 16-neuron groups (caps live registers)
    u64 z = 0ULL;
    #pragma unroll
    for (int g = 0; g < 2; g++) {
        const int off = g * 16;
        u64 b[16];
        {
            const float4* bv = (const float4*)(cW.m1b2 + off);
            #pragma unroll
            for (int j4 = 0; j4 < 4; j4++) {
                float4 bb = bv[j4];
                b[4*j4+0]=dup2(bb.x); b[4*j4+1]=dup2(bb.y);
                b[4*j4+2]=dup2(bb.z); b[4*j4+3]=dup2(bb.w);
            }
        }
        #pragma unroll
        for (int i = 0; i < 32; i++) {
            u64 ai = acc[i];
            const float4* wr = (const float4*)(cW.m1w2 + i * 32 + off);
            #pragma unroll
            for (int j4 = 0; j4 < 4; j4++) {
                float4 w = wr[j4];
                b[4*j4+0] = ffma2(ai, dup2(w.x), b[4*j4+0]);
                b[4*j4+1] = ffma2(ai, dup2(w.y), b[4*j4+1]);
                b[4*j4+2] = ffma2(ai, dup2(w.z), b[4*j4+2]);
                b[4*j4+3] = ffma2(ai, dup2(w.w), b[4*j4+3]);
            }
        }
        const float4* wv = (const float4*)(cW.m1w3 + off);
        #pragma unroll
        for (int j4 = 0; j4 < 4; j4++) {
            float4 w = wv[j4];
            z = ffma2(relu2(b[4*j4+0]), dup2(w.x), z);
            z = ffma2(relu2(b[4*j4+1]), dup2(w.y), z);
            z = ffma2(relu2(b[4*j4+2]), dup2(w.z), z);
            z = ffma2(relu2(b[4*j4+3]), dup2(w.w), z);
        }
    }
    float zl, zh; upk2(z, zl, zh);
    sA = fast_sigmoid(zl + cW.m1b3);
    sB = fast_sigmoid(zh + cW.m1b3);
}

// Update MLP [x1,h(8),agg](10) -> 32 -> relu -> 8 -> relu -> tanh (both nodes)
__device__ __forceinline__ void mlp2_pair(const u64 in2[10], u64 hd[HH]) {
    u64 acc[32];
    {
        const float4* bv = (const float4*)cW.m2b1;
        #pragma unroll
        for (int j4 = 0; j4 < 8; j4++) {
            float4 bb = bv[j4];
            acc[4*j4+0]=dup2(bb.x); acc[4*j4+1]=dup2(bb.y);
            acc[4*j4+2]=dup2(bb.z); acc[4*j4+3]=dup2(bb.w);
        }
    }
    #pragma unroll
    for (int i = 0; i < 10; i++) {
        u64 vi = in2[i];
        const float4* wr = (const float4*)(cW.m2w1 + i * 32);
        #pragma unroll
        for (int j4 = 0; j4 < 8; j4++) {
            float4 w = wr[j4];
            acc[4*j4+0] = ffma2(vi, dup2(w.x), acc[4*j4+0]);
            acc[4*j4+1] = ffma2(vi, dup2(w.y), acc[4*j4+1]);
            acc[4*j4+2] = ffma2(vi, dup2(w.z), acc[4*j4+2]);
            acc[4*j4+3] = ffma2(vi, dup2(w.w), acc[4*j4+3]);
        }
    }
    #pragma unroll
    for (int j = 0; j < 32; j++) acc[j] = relu2(acc[j]);

    u64 b8[8];
    {
        const float4* bv = (const float4*)cW.m2b2;
        float4 b0 = bv[0], b1 = bv[1];
        b8[0]=dup2(b0.x); b8[1]=dup2(b0.y); b8[2]=dup2(b0.z); b8[3]=dup2(b0.w);
        b8[4]=dup2(b1.x); b8[5]=dup2(b1.y); b8[6]=dup2(b1.z); b8[7]=dup2(b1.w);
    }
    #pragma unroll
    for (int i = 0; i < 32; i++) {
        u64 ai = acc[i];
        const float4* wr = (const float4*)(cW.m2w2 + i * 8);
        float4 w0 = wr[0], w1 = wr[1];
        b8[0] = ffma2(ai, dup2(w0.x), b8[0]);
        b8[1] = ffma2(ai, dup2(w0.y), b8[1]);
        b8[2] = ffma2(ai, dup2(w0.z), b8[2]);
        b8[3] = ffma2(ai, dup2(w0.w), b8[3]);
        b8[4] = ffma2(ai, dup2(w1.x), b8[4]);
        b8[5] = ffma2(ai, dup2(w1.y), b8[5]);
        b8[6] = ffma2(ai, dup2(w1.z), b8[6]);
        b8[7] = ffma2(ai, dup2(w1.w), b8[7]);
    }
    // hidden_new = tanh(relu(z2)) per node half
    #pragma unroll
    for (int k = 0; k < HH; k++) {
        float lo, hi; upk2(relu2(b8[k]), lo, hi);
        hd[k] = pk2(fast_tanh_nonneg(lo), fast_tanh_nonneg(hi));
    }
}

// Readout hidden(8) -> 16 -> relu -> 1 -> sigmoid (both nodes)
__device__ __forceinline__ void node_out_pair(const u64 hd[HH],
                                              float& oA, float& oB) {
    u64 o[16];
    {
        const float4* bv = (const float4*)cW.ob1;
        #pragma unroll
        for (int m4 = 0; m4 < 4; m4++) {
            float4 bb = bv[m4];
            o[4*m4+0]=dup2(bb.x); o[4*m4+1]=dup2(bb.y);
            o[4*m4+2]=dup2(bb.z); o[4*m4+3]=dup2(bb.w);
        }
    }
    #pragma unroll
    for (int i = 0; i < HH; i++) {
        u64 hi = hd[i];
        const float4* wr = (const float4*)(cW.ow1 + i * 16);
        #pragma unroll
        for (int m4 = 0; m4 < 4; m4++) {
            float4 w = wr[m4];
            o[4*m4+0] = ffma2(hi, dup2(w.x), o[4*m4+0]);
            o[4*m4+1] = ffma2(hi, dup2(w.y), o[4*m4+1]);
            o[4*m4+2] = ffma2(hi, dup2(w.z), o[4*m4+2]);
            o[4*m4+3] = ffma2(hi, dup2(w.w), o[4*m4+3]);
        }
    }
    u64 z = 0ULL;
    {
        const float4* wv = (const float4*)cW.ow2;
        #pragma unroll
        for (int m4 = 0; m4 < 4; m4++) {
            float4 w = wv[m4];
            z = ffma2(relu2(o[4*m4+0]), dup2(w.x), z);
            z = ffma2(relu2(o[4*m4+1]), dup2(w.y), z);
            z = ffma2(relu2(o[4*m4+2]), dup2(w.z), z);
            z = ffma2(relu2(o[4*m4+3]), dup2(w.w), z);
        }
    }
    float zl, zh; upk2(z, zl, zh);
    oA = fast_sigmoid(zl + cW.ob2);
    oB = fast_sigmoid(zh + cW.ob2);
}

// ---------------- kernels ----------------

// One-time: transposes + hidden zero + frame-0 prologue (s, agg).
__global__ void setup_kernel(const float* __restrict__ ea,
                             const float* __restrict__ x) {
    int e = blockIdx.x * blockDim.x + threadIdx.x;
    if (e < EE) {
        #pragma unroll
        for (int t = 0; t < TT; t++) g_eaT[t * EE + e] = ea[e * TT + t];
    }
    if (e < HH * NPAIR) g_hpack[e] = 0ULL;
    if (e < NN) {
        float x00 = 0.0f;
        #pragma unroll
        for (int t = 0; t < TT; t++) {
            float2 v = ((const float2*)x)[e * TT + t];
            g_x0T[t * NN + e] = v.x;
            g_x1T[t * NN + e] = v.y;
            if (t == 0) x00 = v.x;
        }
        // prologue: s_0 = mlp1(x0, h=0). Use pair path with self-pair; take lane A.
        u64 h0[HH] = {0ULL,0ULL,0ULL,0ULL,0ULL,0ULL,0ULL,0ULL};
        float sA, sB;
        mlp1_pair(dup2(x00), h0, sA, sB);
        g_s[e] = sA;
        g_agg[e] = 0.0f;
    }
}

// Per-frame edge scatter: agg[dst] += s[src] * ea ; 4 edges per thread.
__global__ void edge_kernel(const int* __restrict__ ei, int t) {
    int e4 = blockIdx.x * blockDim.x + threadIdx.x;
    if (e4 >= EE / 4) return;
    int4 s4 = ((const int4*)(ei + t * EE))[e4];
    int4 d4 = ((const int4*)(ei + (TT + t) * EE))[e4];
    float4 a4 = ((const float4*)(g_eaT + t * EE))[e4];
    atomicAdd(&g_agg[d4.x], __ldg(&g_s[s4.x]) * a4.x);
    atomicAdd(&g_agg[d4.y], __ldg(&g_s[s4.y]) * a4.y);
    atomicAdd(&g_agg[d4.z], __ldg(&g_s[s4.z]) * a4.z);
    atomicAdd(&g_agg[d4.w], __ldg(&g_s[s4.w]) * a4.w);
}

// Per-frame node update, 2 nodes (p, p+NPAIR) per thread, f32x2-node-packed.
__global__ void __launch_bounds__(UPD_THR) update_kernel(float* __restrict__ out, int t) {
    int p = blockIdx.x * UPD_THR + threadIdx.x;
    if (p >= NPAIR) return;

    u64 hd[HH];
    #pragma unroll
    for (int i = 0; i < HH; i++) hd[i] = g_hpack[i * NPAIR + p];

    u64 in2[10];
    in2[0] = pk2(g_x1T[t * NN + p], g_x1T[t * NN + p + NPAIR]);
    #pragma unroll
    for (int i = 0; i < HH; i++) in2[1 + i] = hd[i];
    in2[9] = pk2(g_agg[p], g_agg[p + NPAIR]);  // identity norm (mean 0, var 1)

    mlp2_pair(in2, hd);

    #pragma unroll
    for (int i = 0; i < HH; i++) g_hpack[i * NPAIR + p] = hd[i];

    float oA, oB;
    node_out_pair(hd, oA, oB);
    out[t * NN + p]         = oA;
    out[t * NN + p + NPAIR] = oB;

    if (t < TT - 1) {
        u64 x0 = pk2(g_x0T[(t + 1) * NN + p], g_x0T[(t + 1) * NN + p + NPAIR]);
        float sA, sB;
        mlp1_pair(x0, hd, sA, sB);
        g_s[p]          = sA;
        g_s[p + NPAIR]  = sB;
        g_agg[p]         = 0.0f;
        g_agg[p + NPAIR] = 0.0f;
    }
}

// ---------------- launch ----------------
extern "C" void kernel_launch(void* const* d_in, const int* in_sizes, int n_in,
                              void* d_out, int out_size) {
    const float* x  = (const float*)d_in[0];
    const int*   ei = (const int*)d_in[1];
    const float* ea = (const float*)d_in[2];
    WPtrs p;
    p.m1w1 = (const float*)d_in[3];  p.m1b1 = (const float*)d_in[4];
    p.m1w2 = (const float*)d_in[5];  p.m1b2 = (const float*)d_in[6];
    p.m1w3 = (const float*)d_in[7];  p.m1b3 = (const float*)d_in[8];
    p.m2w1 = (const float*)d_in[9];  p.m2b1 = (const float*)d_in[10];
    p.m2w2 = (const float*)d_in[11]; p.m2b2 = (const float*)d_in[12];
    p.ow1  = (const float*)d_in[13]; p.ob1  = (const float*)d_in[14];
    p.ow2  = (const float*)d_in[15]; p.ob2  = (const float*)d_in[16];
    float* out = (float*)d_out;

    // Stage weights, then copy into the constant bank (graph-capture legal).
    pack_weights_kernel<<<1, 256>>>(p);
    void* cw_addr = nullptr;
    void* st_addr = nullptr;
    cudaGetSymbolAddress(&cw_addr, cW);
    cudaGetSymbolAddress(&st_addr, g_wstage);
    cudaMemcpyAsync(cw_addr, st_addr, sizeof(Weights), cudaMemcpyDeviceToDevice, 0);

    setup_kernel<<<(EE + 255) / 256, 256>>>(ea, x);
    for (int t = 0; t < TT; t++) {
        edge_kernel<<<(EE / 4 + 255) / 256, 256>>>(ei, t);
        update_kernel<<<UPD_BLK, UPD_THR>>>(out, t);
    }
}